// round 5
// baseline (speedup 1.0000x reference)
#include <cuda_runtime.h>

#define MARGIN 9.0f
#define NB  32
#define NEI 100000
#define ND  64
#define TPB 128
#define EPB 256

typedef unsigned long long u64;

__device__ __forceinline__ u64 pack2(float x, float y) {
    u64 r; asm("mov.b64 %0, {%1, %2};" : "=l"(r) : "f"(x), "f"(y)); return r;
}
__device__ __forceinline__ void unpack2(u64 v, float& x, float& y) {
    asm("mov.b64 {%0, %1}, %2;" : "=f"(x), "=f"(y) : "l"(v));
}
// packed 2x fp32 FMA (sm_100+): d = a*b + d elementwise on f32 pairs
__device__ __forceinline__ void ffma2(u64& d, u64 a, u64 b) {
    asm("fma.rn.f32x2 %0, %1, %2, %0;" : "+l"(d) : "l"(a), "l"(b));
}

extern __shared__ __align__(16) unsigned char smem_raw[];

// smem layout (dynamic, 83072 B):
//   est   [ND][EPB] float  : 65536 B  (entity tile, d-major, contiguous)
//   qsp   [ND][NB]  u64    : 16384 B  (q pre-splatted (q,q) pairs)
//   enorm [EPB]     float  :  1024 B
//   qn    [NB]      float  :   128 B
#define SMEM_BYTES (ND*EPB*4 + ND*NB*8 + EPB*4 + NB*4)

__global__ void __launch_bounds__(TPB, 2) transe_kernel(
    const void* __restrict__ subp, const void* __restrict__ relp,
    const float* __restrict__ emb_e, const float* __restrict__ emb_rel,
    float* __restrict__ out)
{
    float* est   = (float*)smem_raw;
    u64*   qsp   = (u64*)(smem_raw + ND * EPB * 4);
    float* enorm = (float*)(smem_raw + ND * EPB * 4 + ND * NB * 8);
    float* qn    = enorm + EPB;

    const int tid = threadIdx.x;

    // ---- index dtype detection (jnp.int64 may silently be int32) ----
    bool is64 = true;
    {
        const long long* s64 = (const long long*)subp;
        #pragma unroll
        for (int i = 0; i < 8; i++) {
            long long v = s64[i];
            if (v < 0 || v >= NEI) is64 = false;
        }
    }

    // ---- q fill: qsp[d][b] = splat(emb_e[sub[b]][d] + emb_rel[rel[b]][d]) ----
    // 512 float4 jobs (32 b x 16 c), 4 per thread; b = j&31 keeps gmem loads warm.
    #pragma unroll
    for (int it = 0; it < 4; it++) {
        int j = tid + it * TPB;
        int b = j & 31;
        int c = j >> 5;            // 0..15
        long long s = is64 ? ((const long long*)subp)[b] : (long long)((const int*)subp)[b];
        long long r = is64 ? ((const long long*)relp)[b] : (long long)((const int*)relp)[b];
        float4 ve = ((const float4*)emb_e)[s * (ND/4) + c];
        float4 vr = ((const float4*)emb_rel)[r * (ND/4) + c];
        float q0 = ve.x + vr.x, q1 = ve.y + vr.y, q2 = ve.z + vr.z, q3 = ve.w + vr.w;
        qsp[(4*c + 0) * NB + b] = pack2(q0, q0);
        qsp[(4*c + 1) * NB + b] = pack2(q1, q1);
        qsp[(4*c + 2) * NB + b] = pack2(q2, q2);
        qsp[(4*c + 3) * NB + b] = pack2(q3, q3);
    }

    // ---- entity tile fill (transposed, d-major) + per-entity norms ----
    long long ebase = (long long)blockIdx.x * EPB;
    const float4* src = (const float4*)emb_e;
    #pragma unroll
    for (int half = 0; half < 2; half++) {
        int erow = tid + half * TPB;          // 0..255
        long long ge = ebase + erow;
        float nrm = 0.f;
        #pragma unroll
        for (int c = 0; c < ND/4; c++) {
            float4 v = make_float4(0.f, 0.f, 0.f, 0.f);
            if (ge < NEI) v = src[ge * (ND/4) + c];
            est[(4*c + 0) * EPB + erow] = v.x;
            est[(4*c + 1) * EPB + erow] = v.y;
            est[(4*c + 2) * EPB + erow] = v.z;
            est[(4*c + 3) * EPB + erow] = v.w;
            nrm = fmaf(v.x, v.x, fmaf(v.y, v.y, fmaf(v.z, v.z, fmaf(v.w, v.w, nrm))));
        }
        enorm[erow] = nrm;
    }
    __syncthreads();

    // ---- ||q_b||^2 by warp 0 ----
    if (tid < NB) {
        float s = 0.f;
        #pragma unroll
        for (int d = 0; d < ND; d++) {
            float x, y; unpack2(qsp[d * NB + tid], x, y);
            s = fmaf(x, x, s);
        }
        qn[tid] = s;
    }
    __syncthreads();

    // ---- thread tile: warp = b-group of 8, lane owns 8 entities (2 x float4 strips) ----
    const int bg = tid >> 5;            // 0..3 : b rows [bg*8, bg*8+8)
    const int ln = tid & 31;
    const int cA = ln * 4;              // entities cA..cA+3   (stride-16B coalesced LDS)
    const int cB = 128 + ln * 4;        // entities cB..cB+3

    // acc[bi][p]: p=0,1 -> entity pairs of strip A; p=2,3 -> strip B
    // init -0.5*(qn+en) so dist^2 = -2*acc after accumulating dot(q,e)
    u64 acc[8][4];
    {
        float eA0 = enorm[cA], eA1 = enorm[cA+1], eA2 = enorm[cA+2], eA3 = enorm[cA+3];
        float eB0 = enorm[cB], eB1 = enorm[cB+1], eB2 = enorm[cB+2], eB3 = enorm[cB+3];
        #pragma unroll
        for (int bi = 0; bi < 8; bi++) {
            float qb = qn[bg * 8 + bi];
            acc[bi][0] = pack2(-0.5f*(qb+eA0), -0.5f*(qb+eA1));
            acc[bi][1] = pack2(-0.5f*(qb+eA2), -0.5f*(qb+eA3));
            acc[bi][2] = pack2(-0.5f*(qb+eB0), -0.5f*(qb+eB1));
            acc[bi][3] = pack2(-0.5f*(qb+eB2), -0.5f*(qb+eB3));
        }
    }

    // ---- main loop: per d, 2 entity LDS.128 + 4 q-broadcast LDS.128 + 32 ffma2 ----
    #pragma unroll 4
    for (int d = 0; d < ND; d++) {
        ulonglong2 eA  = *(const ulonglong2*)(est + d * EPB + cA);
        ulonglong2 eB  = *(const ulonglong2*)(est + d * EPB + cB);
        const ulonglong2* qrow = (const ulonglong2*)(qsp + d * NB + bg * 8);
        ulonglong2 q01 = qrow[0];
        ulonglong2 q23 = qrow[1];
        ulonglong2 q45 = qrow[2];
        ulonglong2 q67 = qrow[3];
        u64 qv[8] = { q01.x, q01.y, q23.x, q23.y, q45.x, q45.y, q67.x, q67.y };
        #pragma unroll
        for (int bi = 0; bi < 8; bi++) {
            ffma2(acc[bi][0], eA.x, qv[bi]);
            ffma2(acc[bi][1], eA.y, qv[bi]);
            ffma2(acc[bi][2], eB.x, qv[bi]);
            ffma2(acc[bi][3], eB.y, qv[bi]);
        }
    }

    // ---- epilogue: out = MARGIN - sqrt(max(-2*acc, 0)) ----
    bool fullA = (ebase + cA + 4 <= NEI);
    bool fullB = (ebase + cB + 4 <= NEI);
    #pragma unroll
    for (int bi = 0; bi < 8; bi++) {
        float oA[4], oB[4];
        {
            float a0, a1;
            unpack2(acc[bi][0], a0, a1);
            oA[0] = MARGIN - sqrtf(fmaxf(-2.f * a0, 0.f));
            oA[1] = MARGIN - sqrtf(fmaxf(-2.f * a1, 0.f));
            unpack2(acc[bi][1], a0, a1);
            oA[2] = MARGIN - sqrtf(fmaxf(-2.f * a0, 0.f));
            oA[3] = MARGIN - sqrtf(fmaxf(-2.f * a1, 0.f));
            unpack2(acc[bi][2], a0, a1);
            oB[0] = MARGIN - sqrtf(fmaxf(-2.f * a0, 0.f));
            oB[1] = MARGIN - sqrtf(fmaxf(-2.f * a1, 0.f));
            unpack2(acc[bi][3], a0, a1);
            oB[2] = MARGIN - sqrtf(fmaxf(-2.f * a0, 0.f));
            oB[3] = MARGIN - sqrtf(fmaxf(-2.f * a1, 0.f));
        }
        float* orow = out + (long long)(bg * 8 + bi) * NEI + ebase;
        if (fullA) {
            *(float4*)(orow + cA) = make_float4(oA[0], oA[1], oA[2], oA[3]);
        } else {
            #pragma unroll
            for (int j = 0; j < 4; j++)
                if (ebase + cA + j < NEI) orow[cA + j] = oA[j];
        }
        if (fullB) {
            *(float4*)(orow + cB) = make_float4(oB[0], oB[1], oB[2], oB[3]);
        } else {
            #pragma unroll
            for (int j = 0; j < 4; j++)
                if (ebase + cB + j < NEI) orow[cB + j] = oB[j];
        }
    }
}

extern "C" void kernel_launch(void* const* d_in, const int* in_sizes, int n_in,
                              void* d_out, int out_size) {
    (void)in_sizes; (void)n_in; (void)out_size;
    const void* sub      = d_in[0];
    const void* rel      = d_in[1];
    const float* emb_e   = (const float*)d_in[2];
    const float* emb_rel = (const float*)d_in[3];
    float* out = (float*)d_out;

    static bool attr_set = false;   // idempotent attribute set (not a memory alloc)
    if (!attr_set) {
        cudaFuncSetAttribute(transe_kernel,
                             cudaFuncAttributeMaxDynamicSharedMemorySize, SMEM_BYTES);
        attr_set = true;
    }

    int grid = (NEI + EPB - 1) / EPB;   // 391 blocks
    transe_kernel<<<grid, TPB, SMEM_BYTES>>>(sub, rel, emb_e, emb_rel, out);
}

// round 7
// speedup vs baseline: 1.0724x; 1.0724x over previous
#include <cuda_runtime.h>

#define MARGIN 9.0f
#define NB  32
#define NEI 100000
#define ND  64
#define TPB 256
#define EPB 128

typedef unsigned long long u64;

__device__ __forceinline__ u64 pack2(float x, float y) {
    u64 r; asm("mov.b64 %0, {%1, %2};" : "=l"(r) : "f"(x), "f"(y)); return r;
}
__device__ __forceinline__ void unpack2(u64 v, float& x, float& y) {
    asm("mov.b64 {%0, %1}, %2;" : "=f"(x), "=f"(y) : "l"(v));
}
// packed 2x fp32 FMA (sm_100+): d = a*b + d elementwise on f32 pairs
__device__ __forceinline__ void ffma2(u64& d, u64 a, u64 b) {
    asm("fma.rn.f32x2 %0, %1, %2, %0;" : "+l"(d) : "l"(a), "l"(b));
}

extern __shared__ __align__(16) unsigned char smem_raw[];

// smem layout (41600 B -> 4 blocks/SM):
//   est   [ND][EPB] float : 32768 B  (entity tile, d-major)
//   qp    [ND][NB]  float :  8192 B  (q plain; b-pairs load as ulonglong2)
//   enorm [EPB]     float :   512 B
//   qn    [NB]      float :   128 B
#define EST_BYTES (ND*EPB*4)
#define QP_BYTES  (ND*NB*4)
#define SMEM_BYTES (EST_BYTES + QP_BYTES + EPB*4 + NB*4)

__global__ void __launch_bounds__(TPB, 4) transe_kernel(
    const void* __restrict__ subp, const void* __restrict__ relp,
    const float* __restrict__ emb_e, const float* __restrict__ emb_rel,
    float* __restrict__ out)
{
    float* est   = (float*)smem_raw;
    float* qp    = (float*)(smem_raw + EST_BYTES);
    float* enorm = (float*)(smem_raw + EST_BYTES + QP_BYTES);
    float* qn    = enorm + EPB;

    const int tid = threadIdx.x;
    const long long ebase = (long long)blockIdx.x * EPB;

    if (tid < 128) {
        // ---- entity tile fill: thread-per-row, norm kept in registers ----
        int row = tid;
        long long ge = ebase + row;
        const float4* src = (const float4*)emb_e;
        float nrm = 0.f;
        #pragma unroll
        for (int c = 0; c < ND/4; c++) {
            float4 v = make_float4(0.f, 0.f, 0.f, 0.f);
            if (ge < NEI) v = src[ge * (ND/4) + c];
            est[(4*c + 0) * EPB + row] = v.x;   // lanes -> distinct rows -> conflict-free
            est[(4*c + 1) * EPB + row] = v.y;
            est[(4*c + 2) * EPB + row] = v.z;
            est[(4*c + 3) * EPB + row] = v.w;
            nrm = fmaf(v.x, v.x, fmaf(v.y, v.y, fmaf(v.z, v.z, fmaf(v.w, v.w, nrm))));
        }
        enorm[row] = nrm;
    } else {
        // ---- q fill (concurrent with entity fill): qp[d][b] = e[sub]+r[rel] ----
        // index dtype detection (jnp.int64 may silently be int32); 64B read is
        // in-bounds for both layouts (int32 buffer is 128B).
        bool is64 = true;
        {
            const long long* s64 = (const long long*)subp;
            #pragma unroll
            for (int i = 0; i < 8; i++) {
                long long v = s64[i];
                if (v < 0 || v >= NEI) is64 = false;
            }
        }
        #pragma unroll
        for (int it = 0; it < 4; it++) {
            int j = (tid - 128) + it * 128;   // 0..511 : 32 b x 16 c
            int b = j & 31;
            int c = j >> 5;
            long long s = is64 ? ((const long long*)subp)[b] : (long long)((const int*)subp)[b];
            long long r = is64 ? ((const long long*)relp)[b] : (long long)((const int*)relp)[b];
            float4 ve = ((const float4*)emb_e)[s * (ND/4) + c];
            float4 vr = ((const float4*)emb_rel)[r * (ND/4) + c];
            qp[(4*c + 0) * NB + b] = ve.x + vr.x;
            qp[(4*c + 1) * NB + b] = ve.y + vr.y;
            qp[(4*c + 2) * NB + b] = ve.z + vr.z;
            qp[(4*c + 3) * NB + b] = ve.w + vr.w;
        }
    }
    __syncthreads();

    // ---- ||q_b||^2 by warp 0 ----
    if (tid < NB) {
        float s = 0.f;
        #pragma unroll
        for (int d = 0; d < ND; d++) { float v = qp[d * NB + tid]; s = fmaf(v, v, s); }
        qn[tid] = s;
    }
    __syncthreads();

    // ---- warp tile: 8 b's (4 packed pairs) x 2 entities (splatted) ----
    // Coverage: 4 bg-groups x 8 b = 32 b;  2 eh-halves x 64 = 128 entities. 
    // 256 threads x 16 outputs = 4096 = 32*128.  (R6 bug: covered only 16 b.)
    const int wid = tid >> 5;
    const int ln  = tid & 31;
    const int bg  = wid >> 1;              // 0..3 : b rows [bg*8, bg*8+8)
    const int eh  = wid & 1;               // entity half
    const int eoff = eh * 64 + ln * 2;     // this lane's 2 entities within tile

    // acc[p][j]: p = b-pair (b = bg*8+2p, +1), j = entity; packed along b.
    // init -0.5*(qn+en) so dist^2 = -2*acc after dot accumulation.
    u64 acc[4][2];
    {
        float en0 = enorm[eoff], en1 = enorm[eoff + 1];
        #pragma unroll
        for (int p = 0; p < 4; p++) {
            float qa = qn[bg*8 + 2*p];
            float qb = qn[bg*8 + 2*p + 1];
            acc[p][0] = pack2(-0.5f*(qa+en0), -0.5f*(qb+en0));
            acc[p][1] = pack2(-0.5f*(qa+en1), -0.5f*(qb+en1));
        }
    }

    // ---- main loop: per d = 2 q-broadcast LDS.128 + 1 entity LDS.64
    //                        + 2 splat movs (alu pipe) + 8 independent ffma2 ----
    const float* ep  = est + eoff;
    const float* qpp = qp + bg * 8;
    #pragma unroll 8
    for (int d = 0; d < ND; d++) {
        const ulonglong2* qrow = (const ulonglong2*)(qpp + d * NB);
        ulonglong2 q03 = qrow[0];                 // (q0,q1),(q2,q3) broadcast
        ulonglong2 q47 = qrow[1];                 // (q4,q5),(q6,q7) broadcast
        float2 ee = *(const float2*)(ep + d * EPB);  // 2 entities, contiguous
        u64 e0 = pack2(ee.x, ee.x);
        u64 e1 = pack2(ee.y, ee.y);
        ffma2(acc[0][0], e0, q03.x);
        ffma2(acc[0][1], e1, q03.x);
        ffma2(acc[1][0], e0, q03.y);
        ffma2(acc[1][1], e1, q03.y);
        ffma2(acc[2][0], e0, q47.x);
        ffma2(acc[2][1], e1, q47.x);
        ffma2(acc[3][0], e0, q47.y);
        ffma2(acc[3][1], e1, q47.y);
    }

    // ---- epilogue: out = MARGIN - sqrt(max(-2*acc, 0)); float2 per b, coalesced ----
    long long e0g = ebase + eoff;
    bool full = (e0g + 2 <= NEI);
    #pragma unroll
    for (int p = 0; p < 4; p++) {
        float sa0, sb0, sa1, sb1;
        unpack2(acc[p][0], sa0, sb0);   // (b = bg*8+2p, b+1) at entity 0
        unpack2(acc[p][1], sa1, sb1);   // same b's at entity 1
        float va0 = MARGIN - sqrtf(fmaxf(-2.f * sa0, 0.f));
        float va1 = MARGIN - sqrtf(fmaxf(-2.f * sa1, 0.f));
        float vb0 = MARGIN - sqrtf(fmaxf(-2.f * sb0, 0.f));
        float vb1 = MARGIN - sqrtf(fmaxf(-2.f * sb1, 0.f));
        float* rowa = out + (long long)(bg*8 + 2*p)     * NEI + e0g;
        float* rowb = out + (long long)(bg*8 + 2*p + 1) * NEI + e0g;
        if (full) {
            *(float2*)rowa = make_float2(va0, va1);
            *(float2*)rowb = make_float2(vb0, vb1);
        } else {
            if (e0g < NEI)     { rowa[0] = va0; rowb[0] = vb0; }
            if (e0g + 1 < NEI) { rowa[1] = va1; rowb[1] = vb1; }
        }
    }
}

extern "C" void kernel_launch(void* const* d_in, const int* in_sizes, int n_in,
                              void* d_out, int out_size) {
    (void)in_sizes; (void)n_in; (void)out_size;
    const void* sub      = d_in[0];
    const void* rel      = d_in[1];
    const float* emb_e   = (const float*)d_in[2];
    const float* emb_rel = (const float*)d_in[3];
    float* out = (float*)d_out;

    static bool attr_set = false;   // idempotent attribute set (not a memory alloc)
    if (!attr_set) {
        cudaFuncSetAttribute(transe_kernel,
                             cudaFuncAttributeMaxDynamicSharedMemorySize, SMEM_BYTES);
        attr_set = true;
    }

    int grid = (NEI + EPB - 1) / EPB;   // 782 blocks
    transe_kernel<<<grid, TPB, SMEM_BYTES>>>(sub, rel, emb_e, emb_rel, out);
}

// round 8
// speedup vs baseline: 1.5326x; 1.4290x over previous
#include <cuda_runtime.h>
#include <cuda_bf16.h>
#include <cstdint>

#define MARGIN 9.0f
#define NB  32
#define NEI 100000
#define ND  64
#define TPB 256
#define EPB 128
#define LDR 72        // padded row length in bf16 (144 B): conflict-free ldmatrix/STS

// smem byte offsets
#define SMEM_QH 0                      // qh [32][72] bf16
#define SMEM_QL (SMEM_QH + 32*LDR*2)   // ql [32][72]
#define SMEM_EH (SMEM_QL + 32*LDR*2)   // eh [128][72]
#define SMEM_EL (SMEM_EH + 128*LDR*2)  // el [128][72]
#define SMEM_EN (SMEM_EL + 128*LDR*2)  // enorm [128] f32
#define SMEM_QN (SMEM_EN + 128*4)      // qn [32] f32
#define SMEM_BYTES (SMEM_QN + 32*4)    // = 46720

extern __shared__ __align__(16) unsigned char smem_raw[];

__device__ __forceinline__ void ldsm_x4(uint32_t& r0, uint32_t& r1, uint32_t& r2, uint32_t& r3,
                                        uint32_t addr) {
    asm volatile("ldmatrix.sync.aligned.m8n8.x4.shared.b16 {%0,%1,%2,%3}, [%4];"
                 : "=r"(r0), "=r"(r1), "=r"(r2), "=r"(r3) : "r"(addr));
}
__device__ __forceinline__ void mma_bf16(float* c, const uint32_t* a, uint32_t b0, uint32_t b1) {
    asm volatile("mma.sync.aligned.m16n8k16.row.col.f32.bf16.bf16.f32 "
                 "{%0,%1,%2,%3}, {%4,%5,%6,%7}, {%8,%9}, {%0,%1,%2,%3};"
                 : "+f"(c[0]), "+f"(c[1]), "+f"(c[2]), "+f"(c[3])
                 : "r"(a[0]), "r"(a[1]), "r"(a[2]), "r"(a[3]), "r"(b0), "r"(b1));
}
// split v into bf16 hi + bf16 lo; returns ushort bit patterns
__device__ __forceinline__ void split1(float v, unsigned short& hb, unsigned short& lb) {
    __nv_bfloat16 h = __float2bfloat16_rn(v);
    float hf = __bfloat162float(h);
    __nv_bfloat16 l = __float2bfloat16_rn(v - hf);
    hb = __bfloat16_as_ushort(h);
    lb = __bfloat16_as_ushort(l);
}

__global__ void __launch_bounds__(TPB, 3) transe_kernel(
    const void* __restrict__ subp, const void* __restrict__ relp,
    const float* __restrict__ emb_e, const float* __restrict__ emb_rel,
    float* __restrict__ out)
{
    const int tid = threadIdx.x;
    const long long ebase = (long long)blockIdx.x * EPB;
    float* enorm = (float*)(smem_raw + SMEM_EN);
    float* qn    = (float*)(smem_raw + SMEM_QN);

    if (tid < 128) {
        // ---- entity fill: thread-per-row; fp32 norm; bf16 hi/lo split to smem ----
        int row = tid;
        long long ge = ebase + row;
        const float4* src = (const float4*)emb_e;
        float nrm = 0.f;
        #pragma unroll
        for (int c2 = 0; c2 < 8; c2++) {
            float4 v0 = make_float4(0.f,0.f,0.f,0.f), v1 = v0;
            if (ge < NEI) { v0 = src[ge*16 + 2*c2]; v1 = src[ge*16 + 2*c2 + 1]; }
            float vv[8] = {v0.x,v0.y,v0.z,v0.w, v1.x,v1.y,v1.z,v1.w};
            uint32_t hp[4], lp[4];
            #pragma unroll
            for (int j = 0; j < 4; j++) {
                unsigned short h0,l0,h1,l1;
                split1(vv[2*j],   h0, l0);
                split1(vv[2*j+1], h1, l1);
                hp[j] = (uint32_t)h0 | ((uint32_t)h1 << 16);
                lp[j] = (uint32_t)l0 | ((uint32_t)l1 << 16);
                nrm = fmaf(vv[2*j], vv[2*j], fmaf(vv[2*j+1], vv[2*j+1], nrm));
            }
            *(uint4*)(smem_raw + SMEM_EH + (row*LDR + c2*8)*2) = make_uint4(hp[0],hp[1],hp[2],hp[3]);
            *(uint4*)(smem_raw + SMEM_EL + (row*LDR + c2*8)*2) = make_uint4(lp[0],lp[1],lp[2],lp[3]);
        }
        enorm[row] = nrm;
    } else {
        // ---- q fill: u=0..127; thread owns b = u>>2, dims chunks (u&3) and (u&3)+4 ----
        // index dtype detection (jnp.int64 may silently be int32); 64B read safe.
        bool is64 = true;
        {
            const long long* s64 = (const long long*)subp;
            #pragma unroll
            for (int i = 0; i < 8; i++) {
                long long v = s64[i];
                if (v < 0 || v >= NEI) is64 = false;
            }
        }
        int u = tid - 128;
        int b = u >> 2;
        long long s = is64 ? ((const long long*)subp)[b] : (long long)((const int*)subp)[b];
        long long r = is64 ? ((const long long*)relp)[b] : (long long)((const int*)relp)[b];
        float part = 0.f;
        #pragma unroll
        for (int it = 0; it < 2; it++) {
            int c2 = (u & 3) + it * 4;                    // dims [c2*8, c2*8+8)
            float4 e0 = ((const float4*)emb_e)[s*16 + 2*c2];
            float4 e1 = ((const float4*)emb_e)[s*16 + 2*c2 + 1];
            float4 r0 = ((const float4*)emb_rel)[r*16 + 2*c2];
            float4 r1 = ((const float4*)emb_rel)[r*16 + 2*c2 + 1];
            float vv[8] = {e0.x+r0.x, e0.y+r0.y, e0.z+r0.z, e0.w+r0.w,
                           e1.x+r1.x, e1.y+r1.y, e1.z+r1.z, e1.w+r1.w};
            uint32_t hp[4], lp[4];
            #pragma unroll
            for (int j = 0; j < 4; j++) {
                unsigned short h0,l0,h1,l1;
                split1(vv[2*j],   h0, l0);
                split1(vv[2*j+1], h1, l1);
                hp[j] = (uint32_t)h0 | ((uint32_t)h1 << 16);
                lp[j] = (uint32_t)l0 | ((uint32_t)l1 << 16);
                part = fmaf(vv[2*j], vv[2*j], fmaf(vv[2*j+1], vv[2*j+1], part));
            }
            *(uint4*)(smem_raw + SMEM_QH + (b*LDR + c2*8)*2) = make_uint4(hp[0],hp[1],hp[2],hp[3]);
            *(uint4*)(smem_raw + SMEM_QL + (b*LDR + c2*8)*2) = make_uint4(lp[0],lp[1],lp[2],lp[3]);
        }
        // reduce ||q||^2 across the 4 consecutive lanes owning b
        part += __shfl_down_sync(0xffffffffu, part, 2);
        part += __shfl_down_sync(0xffffffffu, part, 1);
        if ((u & 3) == 0) qn[b] = part;
    }
    __syncthreads();

    // ================= tensor-core main =================
    const int wid = tid >> 5;
    const int ln  = tid & 31;
    const int nbase = wid * 16;          // warp's 16-entity strip

    uint32_t smem_u = (uint32_t)__cvta_generic_to_shared(smem_raw);
    // A (Q) lane address parts: rows m0-15 (lanes 0-15), k +8 for lanes 16-31
    const int arow  = ln & 15;
    const int akoff = (ln >> 4) * 8;
    // B (E) lane parts: M0=(n0-7,k0-7) M1=(n0-7,k8-15) M2=(n8-15,k0-7) M3=(n8-15,k8-15)
    const int brow  = (ln & 7) + ((ln >> 1) & 8);   // +8 when ln>=16
    const int bkoff = (ln & 8);                     // +8 bf16 for lanes 8-15 / 24-31
    uint32_t aH = smem_u + SMEM_QH + (arow*LDR + akoff)*2;
    uint32_t aL = smem_u + SMEM_QL + (arow*LDR + akoff)*2;
    uint32_t bH = smem_u + SMEM_EH + ((nbase + brow)*LDR + bkoff)*2;
    uint32_t bL = smem_u + SMEM_EL + ((nbase + brow)*LDR + bkoff)*2;

    // C init: dist^2 = qn + en - 2*dot  =>  c = -0.5*(qn+en), result = -2*c_final
    const int r0 = ln >> 2;              // row within m16
    const int cb = 2 * (ln & 3);         // col pair within n8
    float c[2][2][4];
    {
        float qv[4] = { qn[r0], qn[r0+8], qn[16+r0], qn[24+r0] };
        #pragma unroll
        for (int nj = 0; nj < 2; nj++) {
            float en0 = enorm[nbase + nj*8 + cb];
            float en1 = enorm[nbase + nj*8 + cb + 1];
            #pragma unroll
            for (int mi = 0; mi < 2; mi++) {
                c[mi][nj][0] = -0.5f*(qv[2*mi]   + en0);
                c[mi][nj][1] = -0.5f*(qv[2*mi]   + en1);
                c[mi][nj][2] = -0.5f*(qv[2*mi+1] + en0);
                c[mi][nj][3] = -0.5f*(qv[2*mi+1] + en1);
            }
        }
    }

    #pragma unroll
    for (int kk = 0; kk < 4; kk++) {
        const uint32_t ko = kk * 32;     // 16 bf16 = 32 B per k-chunk
        uint32_t ah0[4], ah1[4], al0[4], al1[4], bh[4], bl[4];
        ldsm_x4(ah0[0],ah0[1],ah0[2],ah0[3], aH + ko);              // Q hi, m0-15
        ldsm_x4(ah1[0],ah1[1],ah1[2],ah1[3], aH + 16*LDR*2 + ko);   // Q hi, m16-31
        ldsm_x4(al0[0],al0[1],al0[2],al0[3], aL + ko);              // Q lo, m0-15
        ldsm_x4(al1[0],al1[1],al1[2],al1[3], aL + 16*LDR*2 + ko);   // Q lo, m16-31
        ldsm_x4(bh[0],bh[1],bh[2],bh[3], bH + ko);                  // E hi, n0-15
        ldsm_x4(bl[0],bl[1],bl[2],bl[3], bL + ko);                  // E lo, n0-15
        // dot = Ah*Bh + Ah*Bl + Al*Bh   (lo*lo dropped, ~2^-16)
        mma_bf16(c[0][0], ah0, bh[0], bh[1]);
        mma_bf16(c[0][1], ah0, bh[2], bh[3]);
        mma_bf16(c[1][0], ah1, bh[0], bh[1]);
        mma_bf16(c[1][1], ah1, bh[2], bh[3]);
        mma_bf16(c[0][0], ah0, bl[0], bl[1]);
        mma_bf16(c[0][1], ah0, bl[2], bl[3]);
        mma_bf16(c[1][0], ah1, bl[0], bl[1]);
        mma_bf16(c[1][1], ah1, bl[2], bl[3]);
        mma_bf16(c[0][0], al0, bh[0], bh[1]);
        mma_bf16(c[0][1], al0, bh[2], bh[3]);
        mma_bf16(c[1][0], al1, bh[0], bh[1]);
        mma_bf16(c[1][1], al1, bh[2], bh[3]);
    }

    // ---- epilogue: out = MARGIN - sqrt(max(-2c, 0)) ; float2 stores, guarded ----
    #pragma unroll
    for (int mi = 0; mi < 2; mi++) {
        #pragma unroll
        for (int nj = 0; nj < 2; nj++) {
            long long eg = ebase + nbase + nj*8 + cb;
            if (eg < NEI) {   // eg even, NEI even -> pair safe
                int row = mi*16 + r0;
                float v0 = MARGIN - sqrtf(fmaxf(-2.f * c[mi][nj][0], 0.f));
                float v1 = MARGIN - sqrtf(fmaxf(-2.f * c[mi][nj][1], 0.f));
                float v2 = MARGIN - sqrtf(fmaxf(-2.f * c[mi][nj][2], 0.f));
                float v3 = MARGIN - sqrtf(fmaxf(-2.f * c[mi][nj][3], 0.f));
                *(float2*)(out + (long long)row * NEI + eg)       = make_float2(v0, v1);
                *(float2*)(out + (long long)(row + 8) * NEI + eg) = make_float2(v2, v3);
            }
        }
    }
}

extern "C" void kernel_launch(void* const* d_in, const int* in_sizes, int n_in,
                              void* d_out, int out_size) {
    (void)in_sizes; (void)n_in; (void)out_size;
    const void* sub      = d_in[0];
    const void* rel      = d_in[1];
    const float* emb_e   = (const float*)d_in[2];
    const float* emb_rel = (const float*)d_in[3];
    float* out = (float*)d_out;

    static bool attr_set = false;   // idempotent attribute set (not a memory alloc)
    if (!attr_set) {
        cudaFuncSetAttribute(transe_kernel,
                             cudaFuncAttributeMaxDynamicSharedMemorySize, SMEM_BYTES);
        attr_set = true;
    }

    int grid = (NEI + EPB - 1) / EPB;   // 782 blocks
    transe_kernel<<<grid, TPB, SMEM_BYTES>>>(sub, rel, emb_e, emb_rel, out);
}